// round 1
// baseline (speedup 1.0000x reference)
#include <cuda_runtime.h>
#include <cstdint>

// Problem constants (shapes are fixed by the dataset, but N/E derived at runtime)
#define IN_DIM   256
#define OUT_DIM  128
#define MAX_NODES 100000

// Scratch for h = X @ W  (100000 x 128 fp32 = 51.2 MB)
__device__ float g_h[MAX_NODES * OUT_DIM];

// ---------------------------------------------------------------------------
// Kernel 1: SGEMM  h[N,128] = X[N,256] @ W[256,128]
// BM=64, BN=128, BK=16, 128 threads, each thread computes 8x8 outputs.
// ---------------------------------------------------------------------------
__global__ __launch_bounds__(128) void gemm_kernel(
    const float* __restrict__ X, const float* __restrict__ W,
    float* __restrict__ H, int N)
{
    __shared__ float As[16 * 64];    // transposed: As[k][row]
    __shared__ float Bs[16 * 128];   // Bs[k][col]

    const int tid = threadIdx.x;
    const int rowBase = blockIdx.x * 64;

    const int tidRow = tid >> 4;       // 0..7   (8 row groups of 8)
    const int tidCol = tid & 15;       // 0..15  (16 col groups of 8)

    float acc[8][8];
#pragma unroll
    for (int i = 0; i < 8; i++)
#pragma unroll
        for (int j = 0; j < 8; j++) acc[i][j] = 0.0f;

    for (int k0 = 0; k0 < IN_DIM; k0 += 16) {
        // --- load A tile: 64 rows x 16 k  = 256 float4, 2 per thread ---
#pragma unroll
        for (int l = 0; l < 2; l++) {
            int idx = tid + l * 128;          // 0..255
            int row = idx >> 2;               // 0..63
            int c4  = idx & 3;                // 0..3 (float4 within 16 k)
            float4 a;
            int grow = rowBase + row;
            if (grow < N) {
                a = *reinterpret_cast<const float4*>(
                        X + (size_t)grow * IN_DIM + k0 + c4 * 4);
            } else {
                a = make_float4(0.f, 0.f, 0.f, 0.f);
            }
            As[(c4 * 4 + 0) * 64 + row] = a.x;
            As[(c4 * 4 + 1) * 64 + row] = a.y;
            As[(c4 * 4 + 2) * 64 + row] = a.z;
            As[(c4 * 4 + 3) * 64 + row] = a.w;
        }
        // --- load B tile: 16 k x 128 cols = 512 float4, 4 per thread ---
#pragma unroll
        for (int l = 0; l < 4; l++) {
            int idx = tid + l * 128;          // 0..511
            int krow = idx >> 5;              // 0..15
            int c4   = idx & 31;              // 0..31
            float4 bvec = *reinterpret_cast<const float4*>(
                              W + (size_t)(k0 + krow) * OUT_DIM + c4 * 4);
            *reinterpret_cast<float4*>(Bs + krow * 128 + c4 * 4) = bvec;
        }
        __syncthreads();

#pragma unroll
        for (int kk = 0; kk < 16; kk++) {
            float a[8], b[8];
            float4 a0 = *reinterpret_cast<const float4*>(As + kk * 64 + tidRow * 8);
            float4 a1 = *reinterpret_cast<const float4*>(As + kk * 64 + tidRow * 8 + 4);
            a[0]=a0.x; a[1]=a0.y; a[2]=a0.z; a[3]=a0.w;
            a[4]=a1.x; a[5]=a1.y; a[6]=a1.z; a[7]=a1.w;
            float4 b0 = *reinterpret_cast<const float4*>(Bs + kk * 128 + tidCol * 8);
            float4 b1 = *reinterpret_cast<const float4*>(Bs + kk * 128 + tidCol * 8 + 4);
            b[0]=b0.x; b[1]=b0.y; b[2]=b0.z; b[3]=b0.w;
            b[4]=b1.x; b[5]=b1.y; b[6]=b1.z; b[7]=b1.w;
#pragma unroll
            for (int i = 0; i < 8; i++)
#pragma unroll
                for (int j = 0; j < 8; j++)
                    acc[i][j] = fmaf(a[i], b[j], acc[i][j]);
        }
        __syncthreads();
    }

    // --- store ---
#pragma unroll
    for (int i = 0; i < 8; i++) {
        int grow = rowBase + tidRow * 8 + i;
        if (grow < N) {
            float* outp = H + (size_t)grow * OUT_DIM + tidCol * 8;
            *reinterpret_cast<float4*>(outp)     = make_float4(acc[i][0], acc[i][1], acc[i][2], acc[i][3]);
            *reinterpret_cast<float4*>(outp + 4) = make_float4(acc[i][4], acc[i][5], acc[i][6], acc[i][7]);
        }
    }
}

// ---------------------------------------------------------------------------
// Kernel 2: out[n][c] = b[c]  (bias pre-init; atomics accumulate on top)
// ---------------------------------------------------------------------------
__global__ void init_out_kernel(float4* __restrict__ out4,
                                const float4* __restrict__ b4, int n4)
{
    int i = blockIdx.x * blockDim.x + threadIdx.x;
    if (i < n4) {
        out4[i] = b4[i & 31];   // 128 floats = 32 float4 per row
    }
}

// ---------------------------------------------------------------------------
// Kernel 3: scatter-add.  One warp per edge; each lane owns 4 of 128 features.
// out[dst] += val * h[src]  via red.global.add.v4.f32 (fire-and-forget).
// ---------------------------------------------------------------------------
__global__ __launch_bounds__(256) void scatter_kernel(
    const float* __restrict__ h,
    const int* __restrict__ src, const int* __restrict__ dst,
    const float* __restrict__ vals,
    float* __restrict__ out, int E)
{
    const int lane   = threadIdx.x & 31;
    const int warp   = (blockIdx.x * blockDim.x + threadIdx.x) >> 5;
    const int nwarps = (gridDim.x * blockDim.x) >> 5;

    for (int e = warp; e < E; e += nwarps) {
        const int   s = __ldg(src + e);
        const int   d = __ldg(dst + e);
        const float v = __ldg(vals + e);

        const float4 hv = *reinterpret_cast<const float4*>(
                              h + (size_t)s * OUT_DIM + lane * 4);
        float4 m;
        m.x = hv.x * v; m.y = hv.y * v; m.z = hv.z * v; m.w = hv.w * v;

        float* p = out + (size_t)d * OUT_DIM + lane * 4;
        asm volatile(
            "red.global.add.v4.f32 [%0], {%1, %2, %3, %4};"
            :: "l"(p), "f"(m.x), "f"(m.y), "f"(m.z), "f"(m.w)
            : "memory");
    }
}

// ---------------------------------------------------------------------------
// Launch
// ---------------------------------------------------------------------------
extern "C" void kernel_launch(void* const* d_in, const int* in_sizes, int n_in,
                              void* d_out, int out_size)
{
    const float* X    = (const float*)d_in[0];   // [N, 256]
    const int*   src  = (const int*)  d_in[1];   // [E]
    const int*   dst  = (const int*)  d_in[2];   // [E]
    const float* vals = (const float*)d_in[3];   // [E]
    const float* W    = (const float*)d_in[4];   // [256, 128]
    const float* b    = (const float*)d_in[5];   // [128]
    float* out = (float*)d_out;                  // [N, 128]

    const int N = in_sizes[0] / IN_DIM;
    const int E = in_sizes[1];

    float* H;
    cudaGetSymbolAddress((void**)&H, g_h);

    // 1) h = X @ W
    gemm_kernel<<<(N + 63) / 64, 128>>>(X, W, H, N);

    // 2) out = b (broadcast)
    {
        int n4 = N * (OUT_DIM / 4);
        init_out_kernel<<<(n4 + 255) / 256, 256>>>(
            (float4*)out, (const float4*)b, n4);
    }

    // 3) out[dst] += vals * h[src]
    scatter_kernel<<<4096, 256>>>(H, src, dst, vals, out, E);
}

// round 2
// speedup vs baseline: 1.3696x; 1.3696x over previous
#include <cuda_runtime.h>
#include <cstdint>

#define IN_DIM    256
#define OUT_DIM   128
#define MAX_NODES 100000
#define MAX_EDGES 3200000

typedef unsigned long long u64;

// ---------------- device scratch (static, no allocation) -------------------
__device__ float g_h[MAX_NODES * OUT_DIM];        // h = X @ W
__device__ int   g_deg[MAX_NODES];                // per-dst degree
__device__ int   g_rowptr[MAX_NODES + 1];         // CSR row pointers (by dst)
__device__ int   g_fill[MAX_NODES];               // working fill cursor
__device__ int   g_bsum[128];                     // scan block sums
__device__ int2  g_esorted[MAX_EDGES];            // (src, val_bits) sorted by dst

// ---------------- f32x2 helpers (Blackwell packed dual-fp32) ---------------
__device__ __forceinline__ u64 pack2(float lo, float hi) {
    u64 r;
    asm("mov.b64 %0, {%1, %2};" : "=l"(r) : "f"(lo), "f"(hi));
    return r;
}
__device__ __forceinline__ void unpack2(u64 v, float& lo, float& hi) {
    asm("mov.b64 {%0, %1}, %2;" : "=f"(lo), "=f"(hi) : "l"(v));
}
__device__ __forceinline__ void ffma2(u64& d, u64 a, u64 b) {
    asm("fma.rn.f32x2 %0, %1, %2, %3;" : "=l"(d) : "l"(a), "l"(b), "l"(d));
}

// ---------------------------------------------------------------------------
// Kernel 1: SGEMM  h[N,128] = X[N,256] @ W[256,128]  with packed f32x2 FMA.
// BM=64, BN=128, BK=16, 128 threads, 8x8 outputs per thread (as 8x4 f32x2).
// ---------------------------------------------------------------------------
__global__ __launch_bounds__(128) void gemm_kernel(
    const float* __restrict__ X, const float* __restrict__ W,
    float* __restrict__ H, int N)
{
    __shared__ float As[16 * 64];    // As[k][row]
    __shared__ float Bs[16 * 128];   // Bs[k][col]

    const int tid = threadIdx.x;
    const int rowBase = blockIdx.x * 64;
    const int tidRow = tid >> 4;       // 0..7
    const int tidCol = tid & 15;       // 0..15

    u64 acc2[8][4];
#pragma unroll
    for (int i = 0; i < 8; i++)
#pragma unroll
        for (int j = 0; j < 4; j++) acc2[i][j] = 0ull;   // (0.0f, 0.0f)

    for (int k0 = 0; k0 < IN_DIM; k0 += 16) {
        // load A tile: 64 rows x 16 k
#pragma unroll
        for (int l = 0; l < 2; l++) {
            int idx = tid + l * 128;
            int row = idx >> 2;
            int c4  = idx & 3;
            float4 a;
            int grow = rowBase + row;
            if (grow < N) {
                a = *reinterpret_cast<const float4*>(
                        X + (size_t)grow * IN_DIM + k0 + c4 * 4);
            } else {
                a = make_float4(0.f, 0.f, 0.f, 0.f);
            }
            As[(c4 * 4 + 0) * 64 + row] = a.x;
            As[(c4 * 4 + 1) * 64 + row] = a.y;
            As[(c4 * 4 + 2) * 64 + row] = a.z;
            As[(c4 * 4 + 3) * 64 + row] = a.w;
        }
        // load B tile: 16 k x 128 cols
#pragma unroll
        for (int l = 0; l < 4; l++) {
            int idx = tid + l * 128;
            int krow = idx >> 5;
            int c4   = idx & 31;
            float4 bvec = *reinterpret_cast<const float4*>(
                              W + (size_t)(k0 + krow) * OUT_DIM + c4 * 4);
            *reinterpret_cast<float4*>(Bs + krow * 128 + c4 * 4) = bvec;
        }
        __syncthreads();

#pragma unroll
        for (int kk = 0; kk < 16; kk++) {
            float4 a0 = *reinterpret_cast<const float4*>(As + kk * 64 + tidRow * 8);
            float4 a1 = *reinterpret_cast<const float4*>(As + kk * 64 + tidRow * 8 + 4);
            u64 a2[8];
            a2[0] = pack2(a0.x, a0.x); a2[1] = pack2(a0.y, a0.y);
            a2[2] = pack2(a0.z, a0.z); a2[3] = pack2(a0.w, a0.w);
            a2[4] = pack2(a1.x, a1.x); a2[5] = pack2(a1.y, a1.y);
            a2[6] = pack2(a1.z, a1.z); a2[7] = pack2(a1.w, a1.w);

            const u64* b2p = reinterpret_cast<const u64*>(Bs + kk * 128 + tidCol * 8);
            u64 b2[4];
            b2[0] = b2p[0]; b2[1] = b2p[1]; b2[2] = b2p[2]; b2[3] = b2p[3];

#pragma unroll
            for (int i = 0; i < 8; i++)
#pragma unroll
                for (int j = 0; j < 4; j++)
                    ffma2(acc2[i][j], a2[i], b2[j]);
        }
        __syncthreads();
    }

    // store
#pragma unroll
    for (int i = 0; i < 8; i++) {
        int grow = rowBase + tidRow * 8 + i;
        if (grow < N) {
            float o[8];
#pragma unroll
            for (int j = 0; j < 4; j++) unpack2(acc2[i][j], o[2 * j], o[2 * j + 1]);
            float* outp = H + (size_t)grow * OUT_DIM + tidCol * 8;
            *reinterpret_cast<float4*>(outp)     = make_float4(o[0], o[1], o[2], o[3]);
            *reinterpret_cast<float4*>(outp + 4) = make_float4(o[4], o[5], o[6], o[7]);
        }
    }
}

// ---------------------------------------------------------------------------
// CSR build: zero -> histogram -> scan(3 kernels) -> permute
// ---------------------------------------------------------------------------
__global__ void zero_deg_kernel(int* __restrict__ deg, int n)
{
    int i = blockIdx.x * blockDim.x + threadIdx.x;
    if (i < n) deg[i] = 0;
}

__global__ void hist_kernel(const int* __restrict__ dst, int* __restrict__ deg, int E)
{
    int e = blockIdx.x * blockDim.x + threadIdx.x;
    if (e < E) atomicAdd(&deg[dst[e]], 1);
}

// 1024-item blocks, exclusive partial scan + block sums
__global__ __launch_bounds__(1024) void scan1_kernel(
    const int* __restrict__ deg, int* __restrict__ partial,
    int* __restrict__ bsum, int n)
{
    __shared__ int sh[1024];
    int gid = blockIdx.x * 1024 + threadIdx.x;
    int v = (gid < n) ? deg[gid] : 0;
    sh[threadIdx.x] = v;
    __syncthreads();
#pragma unroll
    for (int off = 1; off < 1024; off <<= 1) {
        int t = (threadIdx.x >= off) ? sh[threadIdx.x - off] : 0;
        __syncthreads();
        sh[threadIdx.x] += t;
        __syncthreads();
    }
    if (gid < n) partial[gid] = sh[threadIdx.x] - v;   // exclusive
    if (threadIdx.x == 1023) bsum[blockIdx.x] = sh[1023];
}

__global__ __launch_bounds__(128) void scan2_kernel(int* __restrict__ bsum, int nb)
{
    __shared__ int sh[128];
    int v = (threadIdx.x < nb) ? bsum[threadIdx.x] : 0;
    sh[threadIdx.x] = v;
    __syncthreads();
#pragma unroll
    for (int off = 1; off < 128; off <<= 1) {
        int t = (threadIdx.x >= off) ? sh[threadIdx.x - off] : 0;
        __syncthreads();
        sh[threadIdx.x] += t;
        __syncthreads();
    }
    if (threadIdx.x < nb) bsum[threadIdx.x] = sh[threadIdx.x] - v;  // exclusive
}

__global__ void scan3_kernel(int* __restrict__ rowptr, int* __restrict__ fill,
                             const int* __restrict__ bsum, int n, int E)
{
    int gid = blockIdx.x * blockDim.x + threadIdx.x;
    if (gid < n) {
        int v = rowptr[gid] + bsum[gid >> 10];
        rowptr[gid] = v;
        fill[gid] = v;
    }
    if (gid == 0) rowptr[n] = E;
}

__global__ void permute_kernel(
    const int* __restrict__ src, const int* __restrict__ dst,
    const float* __restrict__ val, int* __restrict__ fill,
    int2* __restrict__ es, int E)
{
    int e = blockIdx.x * blockDim.x + threadIdx.x;
    if (e < E) {
        int d = dst[e];
        int pos = atomicAdd(&fill[d], 1);
        es[pos] = make_int2(src[e], __float_as_int(val[e]));
    }
}

// ---------------------------------------------------------------------------
// Gather: one warp per dst node, accumulate in registers, single write + bias.
// ---------------------------------------------------------------------------
__global__ __launch_bounds__(256) void gather_kernel(
    const float* __restrict__ h, const int* __restrict__ rowptr,
    const int2* __restrict__ es, const float* __restrict__ bias,
    float* __restrict__ out, int N)
{
    const int lane = threadIdx.x & 31;
    const int warp = (blockIdx.x * blockDim.x + threadIdx.x) >> 5;
    const int nw   = (gridDim.x * blockDim.x) >> 5;

    const float4 bv = *reinterpret_cast<const float4*>(bias + lane * 4);

    for (int d = warp; d < N; d += nw) {
        const int beg = rowptr[d];
        const int end = rowptr[d + 1];
        float4 acc = bv;
        for (int e = beg; e < end; e++) {
            const int2 ev = __ldg(es + e);
            const float v = __int_as_float(ev.y);
            const float4 hv = *reinterpret_cast<const float4*>(
                                  h + (size_t)ev.x * OUT_DIM + lane * 4);
            acc.x = fmaf(hv.x, v, acc.x);
            acc.y = fmaf(hv.y, v, acc.y);
            acc.z = fmaf(hv.z, v, acc.z);
            acc.w = fmaf(hv.w, v, acc.w);
        }
        *reinterpret_cast<float4*>(out + (size_t)d * OUT_DIM + lane * 4) = acc;
    }
}

// ---------------------------------------------------------------------------
// Launch
// ---------------------------------------------------------------------------
extern "C" void kernel_launch(void* const* d_in, const int* in_sizes, int n_in,
                              void* d_out, int out_size)
{
    const float* X    = (const float*)d_in[0];   // [N, 256]
    const int*   src  = (const int*)  d_in[1];   // [E]
    const int*   dst  = (const int*)  d_in[2];   // [E]
    const float* vals = (const float*)d_in[3];   // [E]
    const float* W    = (const float*)d_in[4];   // [256, 128]
    const float* b    = (const float*)d_in[5];   // [128]
    float* out = (float*)d_out;                  // [N, 128]

    const int N = in_sizes[0] / IN_DIM;
    const int E = in_sizes[1];

    float* H;       cudaGetSymbolAddress((void**)&H,       g_h);
    int*   deg;     cudaGetSymbolAddress((void**)&deg,     g_deg);
    int*   rowptr;  cudaGetSymbolAddress((void**)&rowptr,  g_rowptr);
    int*   fill;    cudaGetSymbolAddress((void**)&fill,    g_fill);
    int*   bsum;    cudaGetSymbolAddress((void**)&bsum,    g_bsum);
    int2*  es;      cudaGetSymbolAddress((void**)&es,      g_esorted);

    const int nb = (N + 1023) / 1024;            // scan blocks (<= 128)

    // GEMM: h = X @ W
    gemm_kernel<<<(N + 63) / 64, 128>>>(X, W, H, N);

    // CSR build (by dst)
    zero_deg_kernel<<<(N + 255) / 256, 256>>>(deg, N);
    hist_kernel<<<(E + 255) / 256, 256>>>(dst, deg, E);
    scan1_kernel<<<nb, 1024>>>(deg, rowptr, bsum, N);
    scan2_kernel<<<1, 128>>>(bsum, nb);
    scan3_kernel<<<(N + 255) / 256, 256>>>(rowptr, fill, bsum, N, E);
    permute_kernel<<<(E + 255) / 256, 256>>>(src, dst, vals, fill, es, E);

    // Gather with fused bias
    gather_kernel<<<(N * 32 + 255) / 256, 256>>>(H, rowptr, es, b, out, N);
}

// round 3
// speedup vs baseline: 1.4172x; 1.0347x over previous
#include <cuda_runtime.h>
#include <cstdint>

#define IN_DIM    256
#define OUT_DIM   128
#define MAX_NODES 100000
#define MAX_EDGES 3200000

typedef unsigned long long u64;

// ---------------- device scratch (static, no allocation) -------------------
__device__ float g_h[MAX_NODES * OUT_DIM];        // h = X @ W
__device__ int   g_deg[MAX_NODES];                // per-dst degree
__device__ int   g_rowptr[MAX_NODES + 1];         // CSR row pointers (by dst)
__device__ int   g_fill[MAX_NODES];               // working fill cursor
__device__ int   g_bsum[128];                     // scan block sums
__device__ int2  g_esorted[MAX_EDGES];            // (src, val_bits) sorted by dst

// ---------------- f32x2 helpers (Blackwell packed dual-fp32) ---------------
__device__ __forceinline__ u64 pack2(float lo, float hi) {
    u64 r;
    asm("mov.b64 %0, {%1, %2};" : "=l"(r) : "f"(lo), "f"(hi));
    return r;
}
__device__ __forceinline__ void unpack2(u64 v, float& lo, float& hi) {
    asm("mov.b64 {%0, %1}, %2;" : "=f"(lo), "=f"(hi) : "l"(v));
}
__device__ __forceinline__ void ffma2(u64& d, u64 a, u64 b) {
    asm("fma.rn.f32x2 %0, %1, %2, %3;" : "=l"(d) : "l"(a), "l"(b), "l"(d));
}

// ---------------------------------------------------------------------------
// Kernel 1: SGEMM  h[N,128] = X[N,256] @ W[256,128]  with packed f32x2 FMA.
// ---------------------------------------------------------------------------
__global__ __launch_bounds__(128) void gemm_kernel(
    const float* __restrict__ X, const float* __restrict__ W,
    float* __restrict__ H, int N)
{
    __shared__ float As[16 * 64];    // As[k][row]
    __shared__ float Bs[16 * 128];   // Bs[k][col]

    const int tid = threadIdx.x;
    const int rowBase = blockIdx.x * 64;
    const int tidRow = tid >> 4;       // 0..7
    const int tidCol = tid & 15;       // 0..15

    u64 acc2[8][4];
#pragma unroll
    for (int i = 0; i < 8; i++)
#pragma unroll
        for (int j = 0; j < 4; j++) acc2[i][j] = 0ull;

    for (int k0 = 0; k0 < IN_DIM; k0 += 16) {
#pragma unroll
        for (int l = 0; l < 2; l++) {
            int idx = tid + l * 128;
            int row = idx >> 2;
            int c4  = idx & 3;
            float4 a;
            int grow = rowBase + row;
            if (grow < N) {
                a = *reinterpret_cast<const float4*>(
                        X + (size_t)grow * IN_DIM + k0 + c4 * 4);
            } else {
                a = make_float4(0.f, 0.f, 0.f, 0.f);
            }
            As[(c4 * 4 + 0) * 64 + row] = a.x;
            As[(c4 * 4 + 1) * 64 + row] = a.y;
            As[(c4 * 4 + 2) * 64 + row] = a.z;
            As[(c4 * 4 + 3) * 64 + row] = a.w;
        }
#pragma unroll
        for (int l = 0; l < 4; l++) {
            int idx = tid + l * 128;
            int krow = idx >> 5;
            int c4   = idx & 31;
            float4 bvec = *reinterpret_cast<const float4*>(
                              W + (size_t)(k0 + krow) * OUT_DIM + c4 * 4);
            *reinterpret_cast<float4*>(Bs + krow * 128 + c4 * 4) = bvec;
        }
        __syncthreads();

#pragma unroll
        for (int kk = 0; kk < 16; kk++) {
            float4 a0 = *reinterpret_cast<const float4*>(As + kk * 64 + tidRow * 8);
            float4 a1 = *reinterpret_cast<const float4*>(As + kk * 64 + tidRow * 8 + 4);
            u64 a2[8];
            a2[0] = pack2(a0.x, a0.x); a2[1] = pack2(a0.y, a0.y);
            a2[2] = pack2(a0.z, a0.z); a2[3] = pack2(a0.w, a0.w);
            a2[4] = pack2(a1.x, a1.x); a2[5] = pack2(a1.y, a1.y);
            a2[6] = pack2(a1.z, a1.z); a2[7] = pack2(a1.w, a1.w);

            const u64* b2p = reinterpret_cast<const u64*>(Bs + kk * 128 + tidCol * 8);
            u64 b2[4];
            b2[0] = b2p[0]; b2[1] = b2p[1]; b2[2] = b2p[2]; b2[3] = b2p[3];

#pragma unroll
            for (int i = 0; i < 8; i++)
#pragma unroll
                for (int j = 0; j < 4; j++)
                    ffma2(acc2[i][j], a2[i], b2[j]);
        }
        __syncthreads();
    }

#pragma unroll
    for (int i = 0; i < 8; i++) {
        int grow = rowBase + tidRow * 8 + i;
        if (grow < N) {
            float o[8];
#pragma unroll
            for (int j = 0; j < 4; j++) unpack2(acc2[i][j], o[2 * j], o[2 * j + 1]);
            float* outp = H + (size_t)grow * OUT_DIM + tidCol * 8;
            *reinterpret_cast<float4*>(outp)     = make_float4(o[0], o[1], o[2], o[3]);
            *reinterpret_cast<float4*>(outp + 4) = make_float4(o[4], o[5], o[6], o[7]);
        }
    }
}

// ---------------------------------------------------------------------------
// CSR build: zero -> histogram -> scan(3 kernels) -> permute
// ---------------------------------------------------------------------------
__global__ void zero_deg_kernel(int* __restrict__ deg, int n)
{
    int i = blockIdx.x * blockDim.x + threadIdx.x;
    if (i < n) deg[i] = 0;
}

__global__ void hist_kernel(const int* __restrict__ dst, int* __restrict__ deg, int E)
{
    int e = blockIdx.x * blockDim.x + threadIdx.x;
    if (e < E) atomicAdd(&deg[dst[e]], 1);
}

__global__ __launch_bounds__(1024) void scan1_kernel(
    const int* __restrict__ deg, int* __restrict__ partial,
    int* __restrict__ bsum, int n)
{
    __shared__ int sh[1024];
    int gid = blockIdx.x * 1024 + threadIdx.x;
    int v = (gid < n) ? deg[gid] : 0;
    sh[threadIdx.x] = v;
    __syncthreads();
#pragma unroll
    for (int off = 1; off < 1024; off <<= 1) {
        int t = (threadIdx.x >= off) ? sh[threadIdx.x - off] : 0;
        __syncthreads();
        sh[threadIdx.x] += t;
        __syncthreads();
    }
    if (gid < n) partial[gid] = sh[threadIdx.x] - v;   // exclusive
    if (threadIdx.x == 1023) bsum[blockIdx.x] = sh[1023];
}

__global__ __launch_bounds__(128) void scan2_kernel(int* __restrict__ bsum, int nb)
{
    __shared__ int sh[128];
    int v = (threadIdx.x < nb) ? bsum[threadIdx.x] : 0;
    sh[threadIdx.x] = v;
    __syncthreads();
#pragma unroll
    for (int off = 1; off < 128; off <<= 1) {
        int t = (threadIdx.x >= off) ? sh[threadIdx.x - off] : 0;
        __syncthreads();
        sh[threadIdx.x] += t;
        __syncthreads();
    }
    if (threadIdx.x < nb) bsum[threadIdx.x] = sh[threadIdx.x] - v;  // exclusive
}

__global__ void scan3_kernel(int* __restrict__ rowptr, int* __restrict__ fill,
                             const int* __restrict__ bsum, int n, int E)
{
    int gid = blockIdx.x * blockDim.x + threadIdx.x;
    if (gid < n) {
        int v = rowptr[gid] + bsum[gid >> 10];
        rowptr[gid] = v;
        fill[gid] = v;
    }
    if (gid == 0) rowptr[n] = E;
}

__global__ void permute_kernel(
    const int* __restrict__ src, const int* __restrict__ dst,
    const float* __restrict__ val, int* __restrict__ fill,
    int2* __restrict__ es, int E)
{
    int e = blockIdx.x * blockDim.x + threadIdx.x;
    if (e < E) {
        int d = dst[e];
        int pos = atomicAdd(&fill[d], 1);
        es[pos] = make_int2(src[e], __float_as_int(val[e]));
    }
}

// ---------------------------------------------------------------------------
// Gather: one warp per dst node; 4-deep software pipeline for L2 latency.
// ---------------------------------------------------------------------------
__global__ __launch_bounds__(256) void gather_kernel(
    const float* __restrict__ h, const int* __restrict__ rowptr,
    const int2* __restrict__ es, const float* __restrict__ bias,
    float* __restrict__ out, int N)
{
    const int lane = threadIdx.x & 31;
    const int warp = (blockIdx.x * blockDim.x + threadIdx.x) >> 5;
    const int nw   = (gridDim.x * blockDim.x) >> 5;

    const float4 bv = *reinterpret_cast<const float4*>(bias + lane * 4);
    const int col4 = lane * 4;

    for (int d = warp; d < N; d += nw) {
        const int beg = rowptr[d];
        const int end = rowptr[d + 1];
        float4 acc = bv;

        int e = beg;
        // 4-wide unroll: issue all edge loads, then all h loads, then FMAs.
        for (; e + 3 < end; e += 4) {
            int2 e0 = __ldg(es + e);
            int2 e1 = __ldg(es + e + 1);
            int2 e2 = __ldg(es + e + 2);
            int2 e3 = __ldg(es + e + 3);
            const float4 h0 = *reinterpret_cast<const float4*>(h + (size_t)e0.x * OUT_DIM + col4);
            const float4 h1 = *reinterpret_cast<const float4*>(h + (size_t)e1.x * OUT_DIM + col4);
            const float4 h2 = *reinterpret_cast<const float4*>(h + (size_t)e2.x * OUT_DIM + col4);
            const float4 h3 = *reinterpret_cast<const float4*>(h + (size_t)e3.x * OUT_DIM + col4);
            const float v0 = __int_as_float(e0.y), v1 = __int_as_float(e1.y);
            const float v2 = __int_as_float(e2.y), v3 = __int_as_float(e3.y);
            acc.x = fmaf(h0.x, v0, acc.x); acc.y = fmaf(h0.y, v0, acc.y);
            acc.z = fmaf(h0.z, v0, acc.z); acc.w = fmaf(h0.w, v0, acc.w);
            acc.x = fmaf(h1.x, v1, acc.x); acc.y = fmaf(h1.y, v1, acc.y);
            acc.z = fmaf(h1.z, v1, acc.z); acc.w = fmaf(h1.w, v1, acc.w);
            acc.x = fmaf(h2.x, v2, acc.x); acc.y = fmaf(h2.y, v2, acc.y);
            acc.z = fmaf(h2.z, v2, acc.z); acc.w = fmaf(h2.w, v2, acc.w);
            acc.x = fmaf(h3.x, v3, acc.x); acc.y = fmaf(h3.y, v3, acc.y);
            acc.z = fmaf(h3.z, v3, acc.z); acc.w = fmaf(h3.w, v3, acc.w);
        }
        for (; e < end; e++) {
            const int2 ev = __ldg(es + e);
            const float v = __int_as_float(ev.y);
            const float4 hv = *reinterpret_cast<const float4*>(h + (size_t)ev.x * OUT_DIM + col4);
            acc.x = fmaf(hv.x, v, acc.x);
            acc.y = fmaf(hv.y, v, acc.y);
            acc.z = fmaf(hv.z, v, acc.z);
            acc.w = fmaf(hv.w, v, acc.w);
        }
        *reinterpret_cast<float4*>(out + (size_t)d * OUT_DIM + col4) = acc;
    }
}

// ---------------------------------------------------------------------------
// Launch: fork-join — GEMM on main stream, CSR build on side stream.
// ---------------------------------------------------------------------------
extern "C" void kernel_launch(void* const* d_in, const int* in_sizes, int n_in,
                              void* d_out, int out_size)
{
    const float* X    = (const float*)d_in[0];   // [N, 256]
    const int*   src  = (const int*)  d_in[1];   // [E]
    const int*   dst  = (const int*)  d_in[2];   // [E]
    const float* vals = (const float*)d_in[3];   // [E]
    const float* W    = (const float*)d_in[4];   // [256, 128]
    const float* b    = (const float*)d_in[5];   // [128]
    float* out = (float*)d_out;                  // [N, 128]

    const int N = in_sizes[0] / IN_DIM;
    const int E = in_sizes[1];

    float* H;       cudaGetSymbolAddress((void**)&H,       g_h);
    int*   deg;     cudaGetSymbolAddress((void**)&deg,     g_deg);
    int*   rowptr;  cudaGetSymbolAddress((void**)&rowptr,  g_rowptr);
    int*   fill;    cudaGetSymbolAddress((void**)&fill,    g_fill);
    int*   bsum;    cudaGetSymbolAddress((void**)&bsum,    g_bsum);
    int2*  es;      cudaGetSymbolAddress((void**)&es,      g_esorted);

    const int nb = (N + 1023) / 1024;            // scan blocks (<= 128)

    // One-time infra objects (no device memory involved).
    static cudaStream_t s_side = nullptr;
    static cudaEvent_t  e_fork = nullptr, e_join = nullptr;
    if (s_side == nullptr) {
        cudaStreamCreateWithFlags(&s_side, cudaStreamNonBlocking);
        cudaEventCreateWithFlags(&e_fork, cudaEventDisableTiming);
        cudaEventCreateWithFlags(&e_join, cudaEventDisableTiming);
    }

    // Fork: side stream handles the CSR build (independent of GEMM).
    cudaEventRecord(e_fork, 0);
    cudaStreamWaitEvent(s_side, e_fork, 0);

    zero_deg_kernel<<<(N + 255) / 256, 256, 0, s_side>>>(deg, N);
    hist_kernel<<<(E + 255) / 256, 256, 0, s_side>>>(dst, deg, E);
    scan1_kernel<<<nb, 1024, 0, s_side>>>(deg, rowptr, bsum, N);
    scan2_kernel<<<1, 128, 0, s_side>>>(bsum, nb);
    scan3_kernel<<<(N + 255) / 256, 256, 0, s_side>>>(rowptr, fill, bsum, N, E);
    permute_kernel<<<(E + 255) / 256, 256, 0, s_side>>>(src, dst, vals, fill, es, E);
    cudaEventRecord(e_join, s_side);

    // Main stream: GEMM h = X @ W (runs concurrently with CSR build).
    gemm_kernel<<<(N + 63) / 64, 128>>>(X, W, H, N);

    // Join, then gather with fused bias.
    cudaStreamWaitEvent(0, e_join, 0);
    gather_kernel<<<(N * 32 + 255) / 256, 256>>>(H, rowptr, es, b, out, N);
}

// round 5
// speedup vs baseline: 2.2358x; 1.5776x over previous
#include <cuda_runtime.h>
#include <cuda_fp16.h>
#include <cstdint>

#define IN_DIM    256
#define OUT_DIM   128
#define MAX_NODES 100000
#define MAX_EDGES 3200000

// ---------------- device scratch (static, no allocation) -------------------
__device__ __half g_hh[MAX_NODES * OUT_DIM];      // h = X @ W in fp16
__device__ float  g_wt[OUT_DIM * IN_DIM];         // W transposed: [128][256]
__device__ int    g_deg[MAX_NODES];
__device__ int    g_rowptr[MAX_NODES + 1];
__device__ int    g_fill[MAX_NODES];
__device__ int    g_bsum[128];
__device__ int2   g_esorted[MAX_EDGES];           // (src, val_bits) sorted by dst

// ---------------------------------------------------------------------------
// W transpose: WT[n][k] = W[k][n]   (tiny: 32K elements)
// ---------------------------------------------------------------------------
__global__ void transpose_w_kernel(const float* __restrict__ W, float* __restrict__ WT)
{
    int i = blockIdx.x * blockDim.x + threadIdx.x;
    if (i < IN_DIM * OUT_DIM) {
        int k = i / OUT_DIM, n = i % OUT_DIM;
        WT[n * IN_DIM + k] = W[i];
    }
}

// ---------------------------------------------------------------------------
// GEMM via mma.sync tf32 (portable tensor-core path; tcgen05 unavailable:
// harness ptxas targets sm_103 without the 'a' feature set).
// BM=128, BN=128, BK=32; 256 threads = 8 warps in 4(m) x 2(n);
// warp tile 32x64 = 2 m-frags x 8 n-frags of m16n8k8.
// Output written directly as fp16.
// ---------------------------------------------------------------------------
#define LDS_STRIDE 36   // 32 + 4 pad: frag LDS conflict-free, 16B-aligned rows

__device__ __forceinline__ uint32_t f2tf32(float f) {
    uint32_t r;
    asm("cvt.rna.tf32.f32 %0, %1;" : "=r"(r) : "f"(f));
    return r;
}

__global__ __launch_bounds__(256) void gemm_mma_kernel(
    const float* __restrict__ X, const float* __restrict__ WT,
    __half* __restrict__ Hh, int N)
{
    __shared__ uint32_t As[128 * LDS_STRIDE];   // [m][k] tf32 bits
    __shared__ uint32_t Bs[128 * LDS_STRIDE];   // [n][k] tf32 bits

    const int tid  = threadIdx.x;
    const int wid  = tid >> 5;
    const int lane = tid & 31;
    const int mw   = wid >> 1;        // 0..3
    const int nw   = wid & 1;         // 0..1
    const int rowBase = blockIdx.x * 128;

    const int qr = lane >> 2;         // 0..7
    const int qc = lane & 3;          // 0..3

    float acc[2][8][4];
#pragma unroll
    for (int mt = 0; mt < 2; mt++)
#pragma unroll
        for (int nt = 0; nt < 8; nt++)
#pragma unroll
            for (int j = 0; j < 4; j++) acc[mt][nt][j] = 0.0f;

    for (int k0 = 0; k0 < IN_DIM; k0 += 32) {
        // --- A tile: 128 rows x 32 k, cvt to tf32 at store ---
#pragma unroll
        for (int l = 0; l < 4; l++) {
            int idx = tid + l * 256;            // 0..1023
            int row = idx >> 3;
            int c4  = (idx & 7) * 4;
            float4 v;
            int grow = rowBase + row;
            if (grow < N)
                v = *reinterpret_cast<const float4*>(X + (size_t)grow * IN_DIM + k0 + c4);
            else
                v = make_float4(0.f, 0.f, 0.f, 0.f);
            uint4 t = make_uint4(f2tf32(v.x), f2tf32(v.y), f2tf32(v.z), f2tf32(v.w));
            *reinterpret_cast<uint4*>(As + row * LDS_STRIDE + c4) = t;
        }
        // --- B tile: 128 n x 32 k from WT[n][k] ---
#pragma unroll
        for (int l = 0; l < 4; l++) {
            int idx = tid + l * 256;
            int n  = idx >> 3;
            int c4 = (idx & 7) * 4;
            float4 v = *reinterpret_cast<const float4*>(WT + (size_t)n * IN_DIM + k0 + c4);
            uint4 t = make_uint4(f2tf32(v.x), f2tf32(v.y), f2tf32(v.z), f2tf32(v.w));
            *reinterpret_cast<uint4*>(Bs + n * LDS_STRIDE + c4) = t;
        }
        __syncthreads();

#pragma unroll
        for (int kk = 0; kk < 32; kk += 8) {
            uint32_t a[2][4];
#pragma unroll
            for (int mt = 0; mt < 2; mt++) {
                int r = mw * 32 + mt * 16 + qr;
                a[mt][0] = As[r * LDS_STRIDE + kk + qc];
                a[mt][1] = As[(r + 8) * LDS_STRIDE + kk + qc];
                a[mt][2] = As[r * LDS_STRIDE + kk + qc + 4];
                a[mt][3] = As[(r + 8) * LDS_STRIDE + kk + qc + 4];
            }
            uint32_t b[8][2];
#pragma unroll
            for (int nt = 0; nt < 8; nt++) {
                int c = nw * 64 + nt * 8 + qr;
                b[nt][0] = Bs[c * LDS_STRIDE + kk + qc];
                b[nt][1] = Bs[c * LDS_STRIDE + kk + qc + 4];
            }
#pragma unroll
            for (int mt = 0; mt < 2; mt++)
#pragma unroll
                for (int nt = 0; nt < 8; nt++) {
                    asm volatile(
                        "mma.sync.aligned.m16n8k8.row.col.f32.tf32.tf32.f32 "
                        "{%0,%1,%2,%3}, {%4,%5,%6,%7}, {%8,%9}, {%0,%1,%2,%3};"
                        : "+f"(acc[mt][nt][0]), "+f"(acc[mt][nt][1]),
                          "+f"(acc[mt][nt][2]), "+f"(acc[mt][nt][3])
                        : "r"(a[mt][0]), "r"(a[mt][1]), "r"(a[mt][2]), "r"(a[mt][3]),
                          "r"(b[nt][0]), "r"(b[nt][1]));
                }
        }
        __syncthreads();
    }

    // --- epilogue: fp16 store.  c0/c1 -> (row, col..col+1), c2/c3 -> row+8 ---
#pragma unroll
    for (int mt = 0; mt < 2; mt++) {
        int r0 = rowBase + mw * 32 + mt * 16 + qr;
        int r1 = r0 + 8;
#pragma unroll
        for (int nt = 0; nt < 8; nt++) {
            int c = nw * 64 + nt * 8 + qc * 2;
            if (r0 < N) {
                __half2 h01 = __floats2half2_rn(acc[mt][nt][0], acc[mt][nt][1]);
                *reinterpret_cast<__half2*>(Hh + (size_t)r0 * OUT_DIM + c) = h01;
            }
            if (r1 < N) {
                __half2 h23 = __floats2half2_rn(acc[mt][nt][2], acc[mt][nt][3]);
                *reinterpret_cast<__half2*>(Hh + (size_t)r1 * OUT_DIM + c) = h23;
            }
        }
    }
}

// ---------------------------------------------------------------------------
// CSR build: zero -> histogram -> scan(3 kernels) -> permute
// ---------------------------------------------------------------------------
__global__ void zero_deg_kernel(int* __restrict__ deg, int n)
{
    int i = blockIdx.x * blockDim.x + threadIdx.x;
    if (i < n) deg[i] = 0;
}

__global__ void hist_kernel(const int* __restrict__ dst, int* __restrict__ deg, int E)
{
    int e = blockIdx.x * blockDim.x + threadIdx.x;
    if (e < E) atomicAdd(&deg[dst[e]], 1);
}

__global__ __launch_bounds__(1024) void scan1_kernel(
    const int* __restrict__ deg, int* __restrict__ partial,
    int* __restrict__ bsum, int n)
{
    __shared__ int sh[1024];
    int gid = blockIdx.x * 1024 + threadIdx.x;
    int v = (gid < n) ? deg[gid] : 0;
    sh[threadIdx.x] = v;
    __syncthreads();
#pragma unroll
    for (int off = 1; off < 1024; off <<= 1) {
        int t = (threadIdx.x >= off) ? sh[threadIdx.x - off] : 0;
        __syncthreads();
        sh[threadIdx.x] += t;
        __syncthreads();
    }
    if (gid < n) partial[gid] = sh[threadIdx.x] - v;
    if (threadIdx.x == 1023) bsum[blockIdx.x] = sh[1023];
}

__global__ __launch_bounds__(128) void scan2_kernel(int* __restrict__ bsum, int nb)
{
    __shared__ int sh[128];
    int v = (threadIdx.x < nb) ? bsum[threadIdx.x] : 0;
    sh[threadIdx.x] = v;
    __syncthreads();
#pragma unroll
    for (int off = 1; off < 128; off <<= 1) {
        int t = (threadIdx.x >= off) ? sh[threadIdx.x - off] : 0;
        __syncthreads();
        sh[threadIdx.x] += t;
        __syncthreads();
    }
    if (threadIdx.x < nb) bsum[threadIdx.x] = sh[threadIdx.x] - v;
}

__global__ void scan3_kernel(int* __restrict__ rowptr, int* __restrict__ fill,
                             const int* __restrict__ bsum, int n, int E)
{
    int gid = blockIdx.x * blockDim.x + threadIdx.x;
    if (gid < n) {
        int v = rowptr[gid] + bsum[gid >> 10];
        rowptr[gid] = v;
        fill[gid] = v;
    }
    if (gid == 0) rowptr[n] = E;
}

__global__ void permute_kernel(
    const int* __restrict__ src, const int* __restrict__ dst,
    const float* __restrict__ val, int* __restrict__ fill,
    int2* __restrict__ es, int E)
{
    int e = blockIdx.x * blockDim.x + threadIdx.x;
    if (e < E) {
        int d = dst[e];
        int pos = atomicAdd(&fill[d], 1);
        es[pos] = make_int2(src[e], __float_as_int(val[e]));
    }
}

// ---------------------------------------------------------------------------
// Gather from fp16 h: one warp per dst node, 4-deep pipeline, fused bias.
// ---------------------------------------------------------------------------
__device__ __forceinline__ void hfma4(float4& acc, uint2 q, float v)
{
    __half2 a = *reinterpret_cast<__half2*>(&q.x);
    __half2 b = *reinterpret_cast<__half2*>(&q.y);
    float2 fa = __half22float2(a);
    float2 fb = __half22float2(b);
    acc.x = fmaf(fa.x, v, acc.x); acc.y = fmaf(fa.y, v, acc.y);
    acc.z = fmaf(fb.x, v, acc.z); acc.w = fmaf(fb.y, v, acc.w);
}

__global__ __launch_bounds__(256) void gather_kernel(
    const __half* __restrict__ h, const int* __restrict__ rowptr,
    const int2* __restrict__ es, const float* __restrict__ bias,
    float* __restrict__ out, int N)
{
    const int lane = threadIdx.x & 31;
    const int warp = (blockIdx.x * blockDim.x + threadIdx.x) >> 5;
    const int nw   = (gridDim.x * blockDim.x) >> 5;

    const float4 bv = *reinterpret_cast<const float4*>(bias + lane * 4);
    const int col4 = lane * 4;

    for (int d = warp; d < N; d += nw) {
        const int beg = rowptr[d];
        const int end = rowptr[d + 1];
        float4 acc = bv;

        int e = beg;
        for (; e + 3 < end; e += 4) {
            int2 e0 = __ldg(es + e);
            int2 e1 = __ldg(es + e + 1);
            int2 e2 = __ldg(es + e + 2);
            int2 e3 = __ldg(es + e + 3);
            uint2 q0 = *reinterpret_cast<const uint2*>(h + (size_t)e0.x * OUT_DIM + col4);
            uint2 q1 = *reinterpret_cast<const uint2*>(h + (size_t)e1.x * OUT_DIM + col4);
            uint2 q2 = *reinterpret_cast<const uint2*>(h + (size_t)e2.x * OUT_DIM + col4);
            uint2 q3 = *reinterpret_cast<const uint2*>(h + (size_t)e3.x * OUT_DIM + col4);
            hfma4(acc, q0, __int_as_float(e0.y));
            hfma4(acc, q1, __int_as_float(e1.y));
            hfma4(acc, q2, __int_as_float(e2.y));
            hfma4(acc, q3, __int_as_float(e3.y));
        }
        for (; e < end; e++) {
            const int2 ev = __ldg(es + e);
            uint2 q = *reinterpret_cast<const uint2*>(h + (size_t)ev.x * OUT_DIM + col4);
            hfma4(acc, q, __int_as_float(ev.y));
        }
        *reinterpret_cast<float4*>(out + (size_t)d * OUT_DIM + col4) = acc;
    }
}

// ---------------------------------------------------------------------------
// Launch: main stream = transpose + mma GEMM; side stream = CSR build.
// ---------------------------------------------------------------------------
extern "C" void kernel_launch(void* const* d_in, const int* in_sizes, int n_in,
                              void* d_out, int out_size)
{
    const float* X    = (const float*)d_in[0];   // [N, 256]
    const int*   src  = (const int*)  d_in[1];   // [E]
    const int*   dst  = (const int*)  d_in[2];   // [E]
    const float* vals = (const float*)d_in[3];   // [E]
    const float* W    = (const float*)d_in[4];   // [256, 128]
    const float* b    = (const float*)d_in[5];   // [128]
    float* out = (float*)d_out;                  // [N, 128]

    const int N = in_sizes[0] / IN_DIM;
    const int E = in_sizes[1];

    __half* Hh;     cudaGetSymbolAddress((void**)&Hh,      g_hh);
    float*  WT;     cudaGetSymbolAddress((void**)&WT,      g_wt);
    int*    deg;    cudaGetSymbolAddress((void**)&deg,     g_deg);
    int*    rowptr; cudaGetSymbolAddress((void**)&rowptr,  g_rowptr);
    int*    fill;   cudaGetSymbolAddress((void**)&fill,    g_fill);
    int*    bsum;   cudaGetSymbolAddress((void**)&bsum,    g_bsum);
    int2*   es;     cudaGetSymbolAddress((void**)&es,      g_esorted);

    const int nb = (N + 1023) / 1024;

    static cudaStream_t s_side = nullptr;
    static cudaEvent_t  e_fork = nullptr, e_join = nullptr;
    if (s_side == nullptr) {
        cudaStreamCreateWithFlags(&s_side, cudaStreamNonBlocking);
        cudaEventCreateWithFlags(&e_fork, cudaEventDisableTiming);
        cudaEventCreateWithFlags(&e_join, cudaEventDisableTiming);
    }

    // Fork: side stream builds CSR (independent of GEMM).
    cudaEventRecord(e_fork, 0);
    cudaStreamWaitEvent(s_side, e_fork, 0);

    zero_deg_kernel<<<(N + 255) / 256, 256, 0, s_side>>>(deg, N);
    hist_kernel<<<(E + 255) / 256, 256, 0, s_side>>>(dst, deg, E);
    scan1_kernel<<<nb, 1024, 0, s_side>>>(deg, rowptr, bsum, N);
    scan2_kernel<<<1, 128, 0, s_side>>>(bsum, nb);
    scan3_kernel<<<(N + 255) / 256, 256, 0, s_side>>>(rowptr, fill, bsum, N, E);
    permute_kernel<<<(E + 255) / 256, 256, 0, s_side>>>(src, dst, vals, fill, es, E);
    cudaEventRecord(e_join, s_side);

    // Main stream: W^T, then tf32 mma GEMM -> fp16 h.
    transpose_w_kernel<<<(IN_DIM * OUT_DIM + 255) / 256, 256>>>(W, WT);
    gemm_mma_kernel<<<(N + 127) / 128, 256>>>(X, WT, Hh, N);

    // Join, then gather with fused bias.
    cudaStreamWaitEvent(0, e_join, 0);
    gather_kernel<<<(N * 32 + 255) / 256, 256>>>(Hh, rowptr, es, b, out, N);
}

// round 6
// speedup vs baseline: 2.3045x; 1.0307x over previous
#include <cuda_runtime.h>
#include <cuda_fp16.h>
#include <cstdint>

#define IN_DIM    256
#define OUT_DIM   128
#define MAX_NODES 100000
#define MAX_EDGES 3200000

// ---------------- device scratch (static, no allocation) -------------------
__device__ __half g_hh[MAX_NODES * OUT_DIM];      // h = X @ W in fp16
__device__ float  g_wt[OUT_DIM * IN_DIM];         // W transposed: [128][256]
__device__ int    g_deg[MAX_NODES];
__device__ int    g_rowptr[MAX_NODES + 1];
__device__ int    g_fill[MAX_NODES];
__device__ int    g_bsum[128];
__device__ int2   g_esorted[MAX_EDGES];           // (src, val_bits) sorted by dst

// ---------------------------------------------------------------------------
// W transpose: WT[n][k] = W[k][n]   (tiny: 32K elements)
// ---------------------------------------------------------------------------
__global__ void transpose_w_kernel(const float* __restrict__ W, float* __restrict__ WT)
{
    int i = blockIdx.x * blockDim.x + threadIdx.x;
    if (i < IN_DIM * OUT_DIM) {
        int k = i / OUT_DIM, n = i % OUT_DIM;
        WT[n * IN_DIM + k] = W[i];
    }
}

// ---------------------------------------------------------------------------
// GEMM via mma.sync tf32 (tcgen05 unavailable: harness ptxas targets sm_103
// without the 'a' feature set).  BM=128, BN=128, BK=32; 8 warps (4m x 2n);
// warp tile 32x64 = 2 x 8 frags of m16n8k8.  Output stored fp16.
// ---------------------------------------------------------------------------
#define LDS_STRIDE 36   // 32 + 4 pad: frag LDS conflict-free, 16B-aligned rows

__device__ __forceinline__ uint32_t f2tf32(float f) {
    uint32_t r;
    asm("cvt.rna.tf32.f32 %0, %1;" : "=r"(r) : "f"(f));
    return r;
}

__global__ __launch_bounds__(256) void gemm_mma_kernel(
    const float* __restrict__ X, const float* __restrict__ WT,
    __half* __restrict__ Hh, int N)
{
    __shared__ uint32_t As[128 * LDS_STRIDE];   // [m][k] tf32 bits
    __shared__ uint32_t Bs[128 * LDS_STRIDE];   // [n][k] tf32 bits

    const int tid  = threadIdx.x;
    const int wid  = tid >> 5;
    const int lane = tid & 31;
    const int mw   = wid >> 1;        // 0..3
    const int nw   = wid & 1;         // 0..1
    const int rowBase = blockIdx.x * 128;

    const int qr = lane >> 2;         // 0..7
    const int qc = lane & 3;          // 0..3

    float acc[2][8][4];
#pragma unroll
    for (int mt = 0; mt < 2; mt++)
#pragma unroll
        for (int nt = 0; nt < 8; nt++)
#pragma unroll
            for (int j = 0; j < 4; j++) acc[mt][nt][j] = 0.0f;

    for (int k0 = 0; k0 < IN_DIM; k0 += 32) {
        // --- A tile: 128 rows x 32 k, cvt to tf32 at store ---
#pragma unroll
        for (int l = 0; l < 4; l++) {
            int idx = tid + l * 256;            // 0..1023
            int row = idx >> 3;
            int c4  = (idx & 7) * 4;
            float4 v;
            int grow = rowBase + row;
            if (grow < N)
                v = *reinterpret_cast<const float4*>(X + (size_t)grow * IN_DIM + k0 + c4);
            else
                v = make_float4(0.f, 0.f, 0.f, 0.f);
            uint4 t = make_uint4(f2tf32(v.x), f2tf32(v.y), f2tf32(v.z), f2tf32(v.w));
            *reinterpret_cast<uint4*>(As + row * LDS_STRIDE + c4) = t;
        }
        // --- B tile: 128 n x 32 k from WT[n][k] ---
#pragma unroll
        for (int l = 0; l < 4; l++) {
            int idx = tid + l * 256;
            int n  = idx >> 3;
            int c4 = (idx & 7) * 4;
            float4 v = *reinterpret_cast<const float4*>(WT + (size_t)n * IN_DIM + k0 + c4);
            uint4 t = make_uint4(f2tf32(v.x), f2tf32(v.y), f2tf32(v.z), f2tf32(v.w));
            *reinterpret_cast<uint4*>(Bs + n * LDS_STRIDE + c4) = t;
        }
        __syncthreads();

#pragma unroll
        for (int kk = 0; kk < 32; kk += 8) {
            uint32_t a[2][4];
#pragma unroll
            for (int mt = 0; mt < 2; mt++) {
                int r = mw * 32 + mt * 16 + qr;
                a[mt][0] = As[r * LDS_STRIDE + kk + qc];
                a[mt][1] = As[(r + 8) * LDS_STRIDE + kk + qc];
                a[mt][2] = As[r * LDS_STRIDE + kk + qc + 4];
                a[mt][3] = As[(r + 8) * LDS_STRIDE + kk + qc + 4];
            }
            uint32_t b[8][2];
#pragma unroll
            for (int nt = 0; nt < 8; nt++) {
                int c = nw * 64 + nt * 8 + qr;
                b[nt][0] = Bs[c * LDS_STRIDE + kk + qc];
                b[nt][1] = Bs[c * LDS_STRIDE + kk + qc + 4];
            }
#pragma unroll
            for (int mt = 0; mt < 2; mt++)
#pragma unroll
                for (int nt = 0; nt < 8; nt++) {
                    asm volatile(
                        "mma.sync.aligned.m16n8k8.row.col.f32.tf32.tf32.f32 "
                        "{%0,%1,%2,%3}, {%4,%5,%6,%7}, {%8,%9}, {%0,%1,%2,%3};"
                        : "+f"(acc[mt][nt][0]), "+f"(acc[mt][nt][1]),
                          "+f"(acc[mt][nt][2]), "+f"(acc[mt][nt][3])
                        : "r"(a[mt][0]), "r"(a[mt][1]), "r"(a[mt][2]), "r"(a[mt][3]),
                          "r"(b[nt][0]), "r"(b[nt][1]));
                }
        }
        __syncthreads();
    }

    // --- epilogue: fp16 store.  c0/c1 -> (row, col..col+1), c2/c3 -> row+8 ---
#pragma unroll
    for (int mt = 0; mt < 2; mt++) {
        int r0 = rowBase + mw * 32 + mt * 16 + qr;
        int r1 = r0 + 8;
#pragma unroll
        for (int nt = 0; nt < 8; nt++) {
            int c = nw * 64 + nt * 8 + qc * 2;
            if (r0 < N) {
                __half2 h01 = __floats2half2_rn(acc[mt][nt][0], acc[mt][nt][1]);
                *reinterpret_cast<__half2*>(Hh + (size_t)r0 * OUT_DIM + c) = h01;
            }
            if (r1 < N) {
                __half2 h23 = __floats2half2_rn(acc[mt][nt][2], acc[mt][nt][3]);
                *reinterpret_cast<__half2*>(Hh + (size_t)r1 * OUT_DIM + c) = h23;
            }
        }
    }
}

// ---------------------------------------------------------------------------
// CSR build: memset -> histogram(x4) -> scan(3 kernels) -> permute(x2)
// ---------------------------------------------------------------------------
__global__ void hist_kernel(const int* __restrict__ dst, int* __restrict__ deg, int E)
{
    int i = (blockIdx.x * blockDim.x + threadIdx.x) * 4;
    if (i + 3 < E) {
        int4 d = *reinterpret_cast<const int4*>(dst + i);
        atomicAdd(&deg[d.x], 1);
        atomicAdd(&deg[d.y], 1);
        atomicAdd(&deg[d.z], 1);
        atomicAdd(&deg[d.w], 1);
    } else {
        for (int e = i; e < E; e++) atomicAdd(&deg[dst[e]], 1);
    }
}

__global__ __launch_bounds__(1024) void scan1_kernel(
    const int* __restrict__ deg, int* __restrict__ partial,
    int* __restrict__ bsum, int n)
{
    __shared__ int sh[1024];
    int gid = blockIdx.x * 1024 + threadIdx.x;
    int v = (gid < n) ? deg[gid] : 0;
    sh[threadIdx.x] = v;
    __syncthreads();
#pragma unroll
    for (int off = 1; off < 1024; off <<= 1) {
        int t = (threadIdx.x >= off) ? sh[threadIdx.x - off] : 0;
        __syncthreads();
        sh[threadIdx.x] += t;
        __syncthreads();
    }
    if (gid < n) partial[gid] = sh[threadIdx.x] - v;
    if (threadIdx.x == 1023) bsum[blockIdx.x] = sh[1023];
}

__global__ __launch_bounds__(128) void scan2_kernel(int* __restrict__ bsum, int nb)
{
    __shared__ int sh[128];
    int v = (threadIdx.x < nb) ? bsum[threadIdx.x] : 0;
    sh[threadIdx.x] = v;
    __syncthreads();
#pragma unroll
    for (int off = 1; off < 128; off <<= 1) {
        int t = (threadIdx.x >= off) ? sh[threadIdx.x - off] : 0;
        __syncthreads();
        sh[threadIdx.x] += t;
        __syncthreads();
    }
    if (threadIdx.x < nb) bsum[threadIdx.x] = sh[threadIdx.x] - v;
}

__global__ void scan3_kernel(int* __restrict__ rowptr, int* __restrict__ fill,
                             const int* __restrict__ bsum, int n, int E)
{
    int gid = blockIdx.x * blockDim.x + threadIdx.x;
    if (gid < n) {
        int v = rowptr[gid] + bsum[gid >> 10];
        rowptr[gid] = v;
        fill[gid] = v;
    }
    if (gid == 0) rowptr[n] = E;
}

__global__ void permute_kernel(
    const int* __restrict__ src, const int* __restrict__ dst,
    const float* __restrict__ val, int* __restrict__ fill,
    int2* __restrict__ es, int E)
{
    int i = (blockIdx.x * blockDim.x + threadIdx.x) * 2;
    if (i + 1 < E) {
        int2   s = *reinterpret_cast<const int2*>(src + i);
        int2   d = *reinterpret_cast<const int2*>(dst + i);
        float2 v = *reinterpret_cast<const float2*>(val + i);
        int p0 = atomicAdd(&fill[d.x], 1);
        int p1 = atomicAdd(&fill[d.y], 1);
        __stcs(es + p0, make_int2(s.x, __float_as_int(v.x)));
        __stcs(es + p1, make_int2(s.y, __float_as_int(v.y)));
    } else if (i < E) {
        int p = atomicAdd(&fill[dst[i]], 1);
        __stcs(es + p, make_int2(src[i], __float_as_int(val[i])));
    }
}

// ---------------------------------------------------------------------------
// Gather from fp16 h: one warp per dst node, 8-deep pipeline, fused bias.
// es via __ldcs (stream), out via __stcs (keep h resident in L2).
// ---------------------------------------------------------------------------
__device__ __forceinline__ void hfma4(float4& acc, uint2 q, float v)
{
    __half2 a = *reinterpret_cast<__half2*>(&q.x);
    __half2 b = *reinterpret_cast<__half2*>(&q.y);
    float2 fa = __half22float2(a);
    float2 fb = __half22float2(b);
    acc.x = fmaf(fa.x, v, acc.x); acc.y = fmaf(fa.y, v, acc.y);
    acc.z = fmaf(fb.x, v, acc.z); acc.w = fmaf(fb.y, v, acc.w);
}

__global__ __launch_bounds__(256) void gather_kernel(
    const __half* __restrict__ h, const int* __restrict__ rowptr,
    const int2* __restrict__ es, const float* __restrict__ bias,
    float* __restrict__ out, int N)
{
    const int lane = threadIdx.x & 31;
    const int warp = (blockIdx.x * blockDim.x + threadIdx.x) >> 5;
    const int nw   = (gridDim.x * blockDim.x) >> 5;

    const float4 bv = *reinterpret_cast<const float4*>(bias + lane * 4);
    const int col4 = lane * 4;

    for (int d = warp; d < N; d += nw) {
        const int beg = rowptr[d];
        const int end = rowptr[d + 1];
        float4 acc = bv;

        int e = beg;
        for (; e + 7 < end; e += 8) {
            int2 ev[8];
#pragma unroll
            for (int j = 0; j < 8; j++) ev[j] = __ldcs(es + e + j);
            uint2 q[8];
#pragma unroll
            for (int j = 0; j < 8; j++)
                q[j] = *reinterpret_cast<const uint2*>(h + (size_t)ev[j].x * OUT_DIM + col4);
#pragma unroll
            for (int j = 0; j < 8; j++) hfma4(acc, q[j], __int_as_float(ev[j].y));
        }
        for (; e < end; e++) {
            const int2 ev = __ldcs(es + e);
            uint2 q = *reinterpret_cast<const uint2*>(h + (size_t)ev.x * OUT_DIM + col4);
            hfma4(acc, q, __int_as_float(ev.y));
        }
        __stcs(reinterpret_cast<float4*>(out + (size_t)d * OUT_DIM + col4), acc);
    }
}

// ---------------------------------------------------------------------------
// Launch.  Submission order chosen so gemm is the 4th kernel launch
// (ncu in this harness profiles launch index 3) while preserving per-stream
// dependency order: side = hist->scan1->scan2->scan3->permute,
// main = transpose->gemm->(join)->gather.
// ---------------------------------------------------------------------------
extern "C" void kernel_launch(void* const* d_in, const int* in_sizes, int n_in,
                              void* d_out, int out_size)
{
    const float* X    = (const float*)d_in[0];   // [N, 256]
    const int*   src  = (const int*)  d_in[1];   // [E]
    const int*   dst  = (const int*)  d_in[2];   // [E]
    const float* vals = (const float*)d_in[3];   // [E]
    const float* W    = (const float*)d_in[4];   // [256, 128]
    const float* b    = (const float*)d_in[5];   // [128]
    float* out = (float*)d_out;                  // [N, 128]

    const int N = in_sizes[0] / IN_DIM;
    const int E = in_sizes[1];

    __half* Hh;     cudaGetSymbolAddress((void**)&Hh,      g_hh);
    float*  WT;     cudaGetSymbolAddress((void**)&WT,      g_wt);
    int*    deg;    cudaGetSymbolAddress((void**)&deg,     g_deg);
    int*    rowptr; cudaGetSymbolAddress((void**)&rowptr,  g_rowptr);
    int*    fill;   cudaGetSymbolAddress((void**)&fill,    g_fill);
    int*    bsum;   cudaGetSymbolAddress((void**)&bsum,    g_bsum);
    int2*   es;     cudaGetSymbolAddress((void**)&es,      g_esorted);

    const int nb = (N + 1023) / 1024;

    static cudaStream_t s_side = nullptr;
    static cudaEvent_t  e_fork = nullptr, e_join = nullptr;
    if (s_side == nullptr) {
        cudaStreamCreateWithFlags(&s_side, cudaStreamNonBlocking);
        cudaEventCreateWithFlags(&e_fork, cudaEventDisableTiming);
        cudaEventCreateWithFlags(&e_join, cudaEventDisableTiming);
    }

    // Fork side stream.
    cudaEventRecord(e_fork, 0);
    cudaStreamWaitEvent(s_side, e_fork, 0);

    // Side: zero degrees (memset node), histogram, first scan stage.
    cudaMemsetAsync(deg, 0, (size_t)N * sizeof(int), s_side);
    hist_kernel<<<(E / 4 + 255) / 256, 256, 0, s_side>>>(dst, deg, E);      // launch 0
    scan1_kernel<<<nb, 1024, 0, s_side>>>(deg, rowptr, bsum, N);            // launch 1

    // Main: transpose, then GEMM (launch index 3 -> ncu profile target).
    transpose_w_kernel<<<(IN_DIM * OUT_DIM + 255) / 256, 256>>>(W, WT);     // launch 2
    gemm_mma_kernel<<<(N + 127) / 128, 256>>>(X, WT, Hh, N);                // launch 3

    // Side: rest of the build.
    scan2_kernel<<<1, 128, 0, s_side>>>(bsum, nb);                          // launch 4
    scan3_kernel<<<(N + 255) / 256, 256, 0, s_side>>>(rowptr, fill, bsum, N, E); // 5
    permute_kernel<<<(E / 2 + 255) / 256, 256, 0, s_side>>>(src, dst, vals, fill, es, E); // 6
    cudaEventRecord(e_join, s_side);

    // Join, then gather with fused bias.
    cudaStreamWaitEvent(0, e_join, 0);
    gather_kernel<<<(N * 32 + 255) / 256, 256>>>(Hh, rowptr, es, b, out, N); // 7
}